// round 3
// baseline (speedup 1.0000x reference)
#include <cuda_runtime.h>
#include <cstdint>

// NeighborAggregation: out[b,n,h] = (q_b @ Vw^T)[n,h] * softmax_m((q_b @ Wc_kT)[n,m])[n,h]
// with Wc = 0.125 * Kw^T Qw folded so K/Q projections + logits become one GEMM.
//
// Shapes: B=4096, N=200, E=H=M=64.
//   d_in[0] query [4096,200,64] f32
//   d_in[1] key   [4096, 64,64] f32
//   d_in[2] Qw [64,64], d_in[3] Kw [64,64], d_in[4] Vw [64,64]
//   d_out [4096,200,64] f32

#define TB 256

__device__ __align__(16) float g_Wc[64 * 64];   // Wc[e'][e] = 0.125 * sum_h Kw[h,e']*Qw[h,e]
__device__ __align__(16) float g_VwT[64 * 64];  // VwT[e][h] = Vw[h][e]

// ---- packed f32x2 helpers (ptxas will not auto-fuse; must be PTX) ----
__device__ __forceinline__ unsigned long long pk2(float x, float y) {
    unsigned long long r;
    asm("mov.b64 %0, {%1, %2};" : "=l"(r) : "f"(x), "f"(y));
    return r;
}
__device__ __forceinline__ void fma2(unsigned long long& d, unsigned long long a, unsigned long long b) {
    asm("fma.rn.f32x2 %0, %1, %2, %0;" : "+l"(d) : "l"(a), "l"(b));
}
__device__ __forceinline__ float2 up2(unsigned long long v) {
    float lo, hi;
    asm("mov.b64 {%0, %1}, %2;" : "=f"(lo), "=f"(hi) : "l"(v));
    return make_float2(lo, hi);
}

// ---- precompute: Wc = 0.125 * Kw^T @ Qw, VwT = Vw^T (tiny; reruns every launch) ----
__global__ void prep_kernel(const float* __restrict__ Qw, const float* __restrict__ Kw,
                            const float* __restrict__ Vw) {
    int t = blockIdx.x * blockDim.x + threadIdx.x;  // 0..4095
    int r = t >> 6, c = t & 63;                     // r = e', c = e
    float s = 0.f;
#pragma unroll
    for (int h = 0; h < 64; h++) s += Kw[h * 64 + r] * Qw[h * 64 + c];
    g_Wc[t] = s * 0.125f;          // fold 1/sqrt(64)
    g_VwT[t] = Vw[c * 64 + r];     // VwT[e=r][h=c]
}

// ---- main fused kernel: one block per batch ----
// smem layout (floats):
//   As  [200][68]  @ 0         (13600)   -- overlapped by Ks/Wcs during stage A
//   Bs  [64][128]  @ 13600     (8192)    -- [KW^T | Vw^T]
//   Ks  [64][68]   @ 0         (4352)
//   Wcs [64][64]   @ 4352      (4096)
#define SMEM_FLOATS (13600 + 8192)

__global__ __launch_bounds__(256, 2) void fused_kernel(const float* __restrict__ q,
                                                       const float* __restrict__ key,
                                                       float* __restrict__ out) {
    extern __shared__ float smf[];
    float* As = smf;
    float* Bs = smf + 13600;
    float* Ks = smf;
    float* Wcs = smf + 4352;

    const int tid = threadIdx.x;
    const int b = blockIdx.x;
    const float* kb = key + (size_t)b * 4096;
    const float* qb = q + (size_t)b * 12800;
    float* outb = out + (size_t)b * 12800;

    // phase 1: key -> Ks (stride 68), g_Wc -> Wcs, g_VwT -> Bs right half
#pragma unroll 1
    for (int i = tid; i < 1024; i += TB) {
        int m = i >> 4, e4 = i & 15;
        *reinterpret_cast<float4*>(&Ks[m * 68 + e4 * 4]) =
            reinterpret_cast<const float4*>(kb)[i];
    }
#pragma unroll 1
    for (int i = tid; i < 1024; i += TB)
        reinterpret_cast<float4*>(Wcs)[i] = reinterpret_cast<const float4*>(g_Wc)[i];
#pragma unroll 1
    for (int i = tid; i < 1024; i += TB) {
        int e = i >> 4, h4 = i & 15;
        *reinterpret_cast<float4*>(&Bs[e * 128 + 64 + h4 * 4]) =
            reinterpret_cast<const float4*>(g_VwT)[i];
    }
    __syncthreads();

    // stage A: KW[m][e] = sum_e' Ks[m][e'] * Wcs[e'][e]  -> Bs[e][m]
    const int txA = tid & 15, tyA = tid >> 4;
    const int m0 = tyA * 4, e0 = txA * 4;
    float accf[4][4];
    {
        unsigned long long acc[4][2] = {};
#pragma unroll
        for (int ep = 0; ep < 64; ep += 4) {
            float4 a[4];
#pragma unroll
            for (int ii = 0; ii < 4; ii++)
                a[ii] = *reinterpret_cast<const float4*>(&Ks[(m0 + ii) * 68 + ep]);
#pragma unroll
            for (int kk = 0; kk < 4; kk++) {
                ulonglong2 w = *reinterpret_cast<const ulonglong2*>(&Wcs[(ep + kk) * 64 + e0]);
#pragma unroll
                for (int ii = 0; ii < 4; ii++) {
                    float av = (kk == 0) ? a[ii].x : (kk == 1) ? a[ii].y : (kk == 2) ? a[ii].z : a[ii].w;
                    unsigned long long a2 = pk2(av, av);
                    fma2(acc[ii][0], a2, w.x);
                    fma2(acc[ii][1], a2, w.y);
                }
            }
        }
#pragma unroll
        for (int ii = 0; ii < 4; ii++) {
            float2 p0 = up2(acc[ii][0]), p1 = up2(acc[ii][1]);
            accf[ii][0] = p0.x; accf[ii][1] = p0.y; accf[ii][2] = p1.x; accf[ii][3] = p1.y;
        }
    }
    __syncthreads();  // all reads of Ks/Wcs done; safe to overwrite with As

    // write stage A result (transposed): Bs[e0+jj][m0..m0+3]
#pragma unroll
    for (int jj = 0; jj < 4; jj++)
        *reinterpret_cast<float4*>(&Bs[(e0 + jj) * 128 + m0]) =
            make_float4(accf[0][jj], accf[1][jj], accf[2][jj], accf[3][jj]);

    // load q_b -> As [200][68]
#pragma unroll 1
    for (int i = tid; i < 3200; i += TB) {
        int n = i >> 4, e4 = i & 15;
        *reinterpret_cast<float4*>(&As[n * 68 + e4 * 4]) =
            reinterpret_cast<const float4*>(qb)[i];
    }
    __syncthreads();

    // main GEMM + softmax-gate epilogue
    // thread (ty, tx): rows rbase..rbase+3, cols j = tx*4..tx*4+3 (logits) and 64+tx*4.. (V)
    const int tx = tid & 15, ty = tid >> 4;

    for (int n0 = 0; n0 < 200; n0 += 64) {
        int rbase = n0 + ty * 4;
        if (rbase >= 200) continue;  // whole warps skip (warp = 2 adjacent ty)
        const float* ap0 = &As[(rbase + 0) * 68];
        const float* ap1 = &As[(rbase + 1) * 68];
        const float* ap2 = &As[(rbase + 2) * 68];
        const float* ap3 = &As[(rbase + 3) * 68];
        unsigned long long accL[4][2] = {};
        unsigned long long accV[4][2] = {};
#pragma unroll
        for (int k0 = 0; k0 < 64; k0 += 4) {
            float4 av[4];
            av[0] = *reinterpret_cast<const float4*>(ap0 + k0);
            av[1] = *reinterpret_cast<const float4*>(ap1 + k0);
            av[2] = *reinterpret_cast<const float4*>(ap2 + k0);
            av[3] = *reinterpret_cast<const float4*>(ap3 + k0);
#pragma unroll
            for (int kk = 0; kk < 4; kk++) {
                const float* bp = &Bs[(k0 + kk) * 128 + tx * 4];
                ulonglong2 bl = *reinterpret_cast<const ulonglong2*>(bp);
                ulonglong2 bv = *reinterpret_cast<const ulonglong2*>(bp + 64);
#pragma unroll
                for (int i = 0; i < 4; i++) {
                    float aval = (kk == 0) ? av[i].x : (kk == 1) ? av[i].y : (kk == 2) ? av[i].z : av[i].w;
                    unsigned long long a2 = pk2(aval, aval);
                    fma2(accL[i][0], a2, bl.x);
                    fma2(accL[i][1], a2, bl.y);
                    fma2(accV[i][0], a2, bv.x);
                    fma2(accV[i][1], a2, bv.y);
                }
            }
        }
        // epilogue: per-row softmax over 64 logits (16-lane xor reduction), gate V
#pragma unroll
        for (int i = 0; i < 4; i++) {
            int r = rbase + i;  // always < 200 here (rbase <= 196)
            float2 l01 = up2(accL[i][0]), l23 = up2(accL[i][1]);
            float2 v01 = up2(accV[i][0]), v23 = up2(accV[i][1]);
            float mx = fmaxf(fmaxf(l01.x, l01.y), fmaxf(l23.x, l23.y));
#pragma unroll
            for (int off = 8; off >= 1; off >>= 1)
                mx = fmaxf(mx, __shfl_xor_sync(0xffffffffu, mx, off));
            float p0 = __expf(l01.x - mx), p1 = __expf(l01.y - mx);
            float p2 = __expf(l23.x - mx), p3 = __expf(l23.y - mx);
            float s = (p0 + p1) + (p2 + p3);
#pragma unroll
            for (int off = 8; off >= 1; off >>= 1)
                s += __shfl_xor_sync(0xffffffffu, s, off);
            float inv = __fdividef(1.0f, s);
            float4 o = make_float4(v01.x * p0 * inv, v01.y * p1 * inv,
                                   v23.x * p2 * inv, v23.y * p3 * inv);
            *reinterpret_cast<float4*>(&outb[(size_t)r * 64 + tx * 4]) = o;
        }
    }
}

extern "C" void kernel_launch(void* const* d_in, const int* in_sizes, int n_in,
                              void* d_out, int out_size) {
    const float* q  = (const float*)d_in[0];
    const float* k  = (const float*)d_in[1];
    const float* Qw = (const float*)d_in[2];
    const float* Kw = (const float*)d_in[3];
    const float* Vw = (const float*)d_in[4];
    float* out = (float*)d_out;

    int B = in_sizes[0] / (200 * 64);  // 4096

    cudaFuncSetAttribute(fused_kernel, cudaFuncAttributeMaxDynamicSharedMemorySize,
                         SMEM_FLOATS * (int)sizeof(float));

    prep_kernel<<<16, 256>>>(Qw, Kw, Vw);
    fused_kernel<<<B, 256, SMEM_FLOATS * sizeof(float)>>>(q, k, out);
}

// round 14
// speedup vs baseline: 1.5669x; 1.5669x over previous
#include <cuda_runtime.h>
#include <cuda_bf16.h>
#include <cstdint>

// out[b,n,h] = (q_b @ Vw^T)[n,h] * softmax_m(q_b @ Wc @ k_b^T)[n,m=h]
// Wc = 0.125*Kw^T Qw folded (prep kernel). Stage A (f32 SIMT): KW = key_b @ Wc.
// Main GEMM: D[208x128] = q_pad @ [KW | Vw]^T via mma.sync m16n8k16 bf16x3
// (3 passes: Ah*Bh + Ah*Bl + Al*Bh; lo*lo dropped, ~2^-16 rel).
// B=4096, N=200, E=H=M=64, f32 I/O. Plain sm_100 target: NO tcgen05/TMEM.

#define TB 256
#define AST 72   // bf16 row stride (144 B) -> conflict-free fragment LDS
#define BST 72

// smem byte offsets
#define OFF_A_HI 0
#define OFF_A_LO 29952                  // 208 rows * 144 B
#define OFF_B_HI 59904                  // 128 rows * 144 B
#define OFF_B_LO 78336
#define SMEM_TOTAL 96768
// f32 scratch aliases the A region (dead before A is written)
#define OFF_KEYF 0                      // Ks  [64][68] f32 = 17408 B
#define OFF_WCF  17408                  // Wcs [64][64] f32 = 16384 B

__device__ __align__(16) float g_Wc[64 * 64];

// ---- packed f32x2 helpers (stage A; proven on this harness in R3) ----
__device__ __forceinline__ unsigned long long pk2(float x, float y) {
    unsigned long long r; asm("mov.b64 %0, {%1, %2};" : "=l"(r) : "f"(x), "f"(y)); return r;
}
__device__ __forceinline__ void fma2(unsigned long long& d, unsigned long long a, unsigned long long b) {
    asm("fma.rn.f32x2 %0, %1, %2, %0;" : "+l"(d) : "l"(a), "l"(b));
}
__device__ __forceinline__ float2 up2(unsigned long long v) {
    float lo, hi; asm("mov.b64 {%0, %1}, %2;" : "=f"(lo), "=f"(hi) : "l"(v));
    return make_float2(lo, hi);
}

// bf16 mma, f32 accum (sm_80+; HMMA on tensor pipe)
__device__ __forceinline__ void mma16816(float* c, uint32_t a0, uint32_t a1,
                                         uint32_t a2, uint32_t a3,
                                         uint32_t b0, uint32_t b1) {
    asm volatile(
        "mma.sync.aligned.m16n8k16.row.col.f32.bf16.bf16.f32 "
        "{%0,%1,%2,%3}, {%4,%5,%6,%7}, {%8,%9}, {%0,%1,%2,%3};"
        : "+f"(c[0]), "+f"(c[1]), "+f"(c[2]), "+f"(c[3])
        : "r"(a0), "r"(a1), "r"(a2), "r"(a3), "r"(b0), "r"(b1));
}

// split 8 f32 -> bf16 hi + bf16 residual lo, 16B packed stores
__device__ __forceinline__ void split8(char* hip, char* lop, const float* v) {
    uint32_t hs[8], ls[8];
#pragma unroll
    for (int j = 0; j < 8; j++) {
        __nv_bfloat16 h = __float2bfloat16_rn(v[j]);
        __nv_bfloat16 l = __float2bfloat16_rn(v[j] - __bfloat162float(h));
        hs[j] = (uint32_t)__bfloat16_as_ushort(h);
        ls[j] = (uint32_t)__bfloat16_as_ushort(l);
    }
    *reinterpret_cast<uint4*>(hip) = make_uint4(hs[0] | (hs[1] << 16), hs[2] | (hs[3] << 16),
                                                hs[4] | (hs[5] << 16), hs[6] | (hs[7] << 16));
    *reinterpret_cast<uint4*>(lop) = make_uint4(ls[0] | (ls[1] << 16), ls[2] | (ls[3] << 16),
                                                ls[4] | (ls[5] << 16), ls[6] | (ls[7] << 16));
}

__global__ void prep_kernel(const float* __restrict__ Qw, const float* __restrict__ Kw) {
    int t = blockIdx.x * blockDim.x + threadIdx.x;  // 0..4095
    int r = t >> 6, c = t & 63;
    float s = 0.f;
#pragma unroll
    for (int h = 0; h < 64; h++) s += Kw[h * 64 + r] * Qw[h * 64 + c];
    g_Wc[t] = s * 0.125f;
}

__global__ __launch_bounds__(256, 2) void fused_kernel(const float* __restrict__ q,
                                                       const float* __restrict__ key,
                                                       const float* __restrict__ Vw,
                                                       float* __restrict__ out) {
    extern __shared__ char smem[];
    const int tid = threadIdx.x;
    const int wid = tid >> 5;
    const int lane = tid & 31;
    const int b = blockIdx.x;
    const float* kb = key + (size_t)b * 4096;
    const float* qb = q + (size_t)b * 12800;
    float* outb = out + (size_t)b * 12800;

    // phase 1: key -> Ks f32 [64][68], Wc -> Wcs f32 [64][64] (alias A region);
    //          Vw -> B rows 64..127 (bf16 hi/lo)
    float* Ks = reinterpret_cast<float*>(smem + OFF_KEYF);
    float* Wcs = reinterpret_cast<float*>(smem + OFF_WCF);
#pragma unroll 1
    for (int i = tid; i < 1024; i += TB) {
        int m = i >> 4, e4 = i & 15;
        *reinterpret_cast<float4*>(&Ks[m * 68 + e4 * 4]) =
            reinterpret_cast<const float4*>(kb)[i];
    }
#pragma unroll 1
    for (int i = tid; i < 1024; i += TB)
        reinterpret_cast<float4*>(Wcs)[i] = reinterpret_cast<const float4*>(g_Wc)[i];
#pragma unroll 1
    for (int i = tid; i < 512; i += TB) {
        int h = i >> 3, c8 = (i & 7) * 8;
        float v[8];
        *reinterpret_cast<float4*>(v) = *reinterpret_cast<const float4*>(Vw + h * 64 + c8);
        *reinterpret_cast<float4*>(v + 4) = *reinterpret_cast<const float4*>(Vw + h * 64 + c8 + 4);
        uint32_t off = (uint32_t)(64 + h) * (BST * 2) + c8 * 2;
        split8(smem + OFF_B_HI + off, smem + OFF_B_LO + off, v);
    }
    __syncthreads();

    // stage A (f32): KW[m][e] = sum_e' Ks[m][e'] * Wcs[e'][e], 4x4 per thread
    const int txA = tid & 15, tyA = tid >> 4;
    const int m0A = tyA * 4, e0A = txA * 4;
    float accf[4][4];
    {
        unsigned long long acc[4][2] = {};
#pragma unroll
        for (int ep = 0; ep < 64; ep += 4) {
            float4 a[4];
#pragma unroll
            for (int ii = 0; ii < 4; ii++)
                a[ii] = *reinterpret_cast<const float4*>(&Ks[(m0A + ii) * 68 + ep]);
#pragma unroll
            for (int kk = 0; kk < 4; kk++) {
                ulonglong2 w = *reinterpret_cast<const ulonglong2*>(&Wcs[(ep + kk) * 64 + e0A]);
#pragma unroll
                for (int ii = 0; ii < 4; ii++) {
                    float av = (kk == 0) ? a[ii].x : (kk == 1) ? a[ii].y
                             : (kk == 2) ? a[ii].z : a[ii].w;
                    unsigned long long a2 = pk2(av, av);
                    fma2(acc[ii][0], a2, w.x);
                    fma2(acc[ii][1], a2, w.y);
                }
            }
        }
#pragma unroll
        for (int ii = 0; ii < 4; ii++) {
            float2 p0 = up2(acc[ii][0]), p1 = up2(acc[ii][1]);
            accf[ii][0] = p0.x; accf[ii][1] = p0.y; accf[ii][2] = p1.x; accf[ii][3] = p1.y;
        }
    }
    // KW -> B rows 0..63 (hi/lo), uint2 8B stores (B region: no scratch alias)
#pragma unroll
    for (int ii = 0; ii < 4; ii++) {
        uint32_t h2[2], l2[2];
#pragma unroll
        for (int jj = 0; jj < 2; jj++) {
            __nv_bfloat16 ha = __float2bfloat16_rn(accf[ii][2 * jj]);
            __nv_bfloat16 hb = __float2bfloat16_rn(accf[ii][2 * jj + 1]);
            __nv_bfloat16 la = __float2bfloat16_rn(accf[ii][2 * jj] - __bfloat162float(ha));
            __nv_bfloat16 lb = __float2bfloat16_rn(accf[ii][2 * jj + 1] - __bfloat162float(hb));
            h2[jj] = (uint32_t)__bfloat16_as_ushort(ha) | ((uint32_t)__bfloat16_as_ushort(hb) << 16);
            l2[jj] = (uint32_t)__bfloat16_as_ushort(la) | ((uint32_t)__bfloat16_as_ushort(lb) << 16);
        }
        uint32_t off = (uint32_t)(m0A + ii) * (BST * 2) + e0A * 2;
        *reinterpret_cast<uint2*>(smem + OFF_B_HI + off) = make_uint2(h2[0], h2[1]);
        *reinterpret_cast<uint2*>(smem + OFF_B_LO + off) = make_uint2(l2[0], l2[1]);
    }
    __syncthreads();  // scratch reads done; A region reusable

    // q -> A rows 0..199 (hi/lo), zero-pad rows 200..207
#pragma unroll 1
    for (int i = tid; i < 1600; i += TB) {
        int n = i >> 3, c8 = (i & 7) * 8;
        float v[8];
        *reinterpret_cast<float4*>(v) = *reinterpret_cast<const float4*>(qb + n * 64 + c8);
        *reinterpret_cast<float4*>(v + 4) = *reinterpret_cast<const float4*>(qb + n * 64 + c8 + 4);
        uint32_t off = (uint32_t)n * (AST * 2) + c8 * 2;
        split8(smem + OFF_A_HI + off, smem + OFF_A_LO + off, v);
    }
#pragma unroll 1
    for (int i = tid; i < 144; i += TB) {
        uint4 z = make_uint4(0, 0, 0, 0);
        if (i < 72)
            *reinterpret_cast<uint4*>(smem + OFF_A_HI + 200 * (AST * 2) + i * 16) = z;
        else
            *reinterpret_cast<uint4*>(smem + OFF_A_LO + 200 * (AST * 2) + (i - 72) * 16) = z;
    }
    __syncthreads();

    // main GEMM: 13 m16-tiles round-robin over 8 warps; 16 n8-tiles; K=64; 3 passes
    const int g = lane >> 2;   // fragment row/col group
    const int c = lane & 3;
#pragma unroll 1
    for (int t = wid; t < 13; t += 8) {
        const int m0 = t * 16;
        float acc[16][4];
#pragma unroll
        for (int nt = 0; nt < 16; nt++) {
            acc[nt][0] = 0.f; acc[nt][1] = 0.f; acc[nt][2] = 0.f; acc[nt][3] = 0.f;
        }
        const uint32_t arow0 = (uint32_t)(m0 + g) * (AST * 2);
        const uint32_t arow8 = (uint32_t)(m0 + g + 8) * (AST * 2);
#pragma unroll
        for (int pass = 0; pass < 3; pass++) {
            const char* Ap = smem + (pass == 2 ? OFF_A_LO : OFF_A_HI);
            const char* Bp = smem + (pass == 1 ? OFF_B_LO : OFF_B_HI);
#pragma unroll
            for (int s = 0; s < 4; s++) {
                const uint32_t kbyte = (uint32_t)(s * 16 + c * 2) * 2;
                uint32_t a0 = *reinterpret_cast<const uint32_t*>(Ap + arow0 + kbyte);
                uint32_t a1 = *reinterpret_cast<const uint32_t*>(Ap + arow8 + kbyte);
                uint32_t a2 = *reinterpret_cast<const uint32_t*>(Ap + arow0 + kbyte + 16);
                uint32_t a3 = *reinterpret_cast<const uint32_t*>(Ap + arow8 + kbyte + 16);
#pragma unroll
                for (int nt = 0; nt < 16; nt++) {
                    const uint32_t brow = (uint32_t)(nt * 8 + g) * (BST * 2);
                    uint32_t b0 = *reinterpret_cast<const uint32_t*>(Bp + brow + kbyte);
                    uint32_t b1 = *reinterpret_cast<const uint32_t*>(Bp + brow + kbyte + 16);
                    mma16816(acc[nt], a0, a1, a2, a3, b0, b1);
                }
            }
        }
        // epilogue: per lane rows r=m0+g (half 0) and r+8 (half 1).
        // logits = acc[0..7] (cols nt*8+2c,+1), V = acc[8..15] at same (h%8) slots.
#pragma unroll
        for (int half = 0; half < 2; half++) {
            const int r = m0 + g + half * 8;
            const int o = half * 2;
            float mx = -1e30f;
#pragma unroll
            for (int nt = 0; nt < 8; nt++)
                mx = fmaxf(mx, fmaxf(acc[nt][o], acc[nt][o + 1]));
            mx = fmaxf(mx, __shfl_xor_sync(0xffffffffu, mx, 1));
            mx = fmaxf(mx, __shfl_xor_sync(0xffffffffu, mx, 2));
            float s = 0.f;
#pragma unroll
            for (int nt = 0; nt < 8; nt++) {
                acc[nt][o] = __expf(acc[nt][o] - mx);         // in place -> p
                acc[nt][o + 1] = __expf(acc[nt][o + 1] - mx);
                s += acc[nt][o] + acc[nt][o + 1];
            }
            s += __shfl_xor_sync(0xffffffffu, s, 1);
            s += __shfl_xor_sync(0xffffffffu, s, 2);
            float inv = __fdividef(1.0f, s);
            if (r < 200) {
                float* orow = outb + (size_t)r * 64;
#pragma unroll
                for (int nt = 0; nt < 8; nt++) {
                    int h = nt * 8 + c * 2;
                    float2 ov = make_float2(acc[nt + 8][o] * acc[nt][o] * inv,
                                            acc[nt + 8][o + 1] * acc[nt][o + 1] * inv);
                    *reinterpret_cast<float2*>(orow + h) = ov;
                }
            }
        }
    }
}

extern "C" void kernel_launch(void* const* d_in, const int* in_sizes, int n_in,
                              void* d_out, int out_size) {
    const float* q  = (const float*)d_in[0];
    const float* k  = (const float*)d_in[1];
    const float* Qw = (const float*)d_in[2];
    const float* Kw = (const float*)d_in[3];
    const float* Vw = (const float*)d_in[4];
    float* out = (float*)d_out;

    int B = in_sizes[0] / (200 * 64);  // 4096

    cudaFuncSetAttribute(fused_kernel, cudaFuncAttributeMaxDynamicSharedMemorySize, SMEM_TOTAL);

    prep_kernel<<<16, 256>>>(Qw, Kw);
    fused_kernel<<<B, 256, SMEM_TOTAL>>>(q, k, Vw, out);
}